// round 4
// baseline (speedup 1.0000x reference)
#include <cuda_runtime.h>

// MultiHeadEMA as a chunked diagonal linear recurrence (no FFT).
// out[b,t,d] = sum_n c[d,n] * h[d,n,t] + omega[d]*x[b,t,d]
// h[t] = q*h[t-1] + x[t],  q = 1 - sigmoid(delta)*sigmoid(alpha),
// c = sigmoid(delta)*beta*gamma*sqrt(1/N)
//
// R3: L2 prefetch (+2 iters ahead), C=32 chunks for wave balance,
// higher occupancy cap on local pass.

#define cB 8
#define cL 4096
#define cD 1024
#define cN 16
#define cC 32            // chunks
#define cS (cL / cC)     // 128 steps per chunk
#define TD 128           // threads per block (1 channel per thread)

typedef unsigned long long u64;

// scratch (static __device__ arrays: no allocations allowed)
__device__ float g_q[cD * cN];
__device__ float g_cc[cD * cN];
__device__ float g_qS[cD * cN];
__device__ float g_Le[(size_t)cB * cC * cD * cN];  // local chunk end states
__device__ float g_P[(size_t)cB * cC * cD * cN];   // prefix (init) states per chunk

__device__ __forceinline__ u64 pack2(float lo, float hi) {
    u64 r; asm("mov.b64 %0,{%1,%2};" : "=l"(r) : "f"(lo), "f"(hi)); return r;
}
__device__ __forceinline__ float2 unpack2(u64 v) {
    float2 f; asm("mov.b64 {%0,%1},%2;" : "=f"(f.x), "=f"(f.y) : "l"(v)); return f;
}
__device__ __forceinline__ u64 fma2(u64 a, u64 b, u64 c) {
    u64 d; asm("fma.rn.f32x2 %0,%1,%2,%3;" : "=l"(d) : "l"(a), "l"(b), "l"(c)); return d;
}
__device__ __forceinline__ u64 mul2(u64 a, u64 b) {
    u64 d; asm("mul.rn.f32x2 %0,%1,%2;" : "=l"(d) : "l"(a), "l"(b)); return d;
}
__device__ __forceinline__ u64 add2(u64 a, u64 b) {
    u64 d; asm("add.rn.f32x2 %0,%1,%2;" : "=l"(d) : "l"(a), "l"(b)); return d;
}
__device__ __forceinline__ void pf_l2(const float* p) {
    asm volatile("prefetch.global.L2 [%0];" :: "l"(p));
}

// ---------------------------------------------------------------------------
// Kernel 0: per-(d,n) coefficients
// ---------------------------------------------------------------------------
__global__ void coeff_kernel(const float* __restrict__ delta,
                             const float* __restrict__ alpha,
                             const float* __restrict__ beta,
                             const float* __restrict__ gamma) {
    int i = blockIdx.x * blockDim.x + threadIdx.x;
    if (i >= cD * cN) return;
    float p  = 1.f / (1.f + expf(-delta[i]));
    float a  = 1.f / (1.f + expf(-alpha[i]));
    float pa = p * a;
    g_q[i]  = 1.f - pa;
    g_cc[i] = p * beta[i] * gamma[i] * 0.25f;               // scale = sqrt(1/16)
    g_qS[i] = expf((float)cS * log1pf(-pa));                // q^S, accurate near q~1
}

// ---------------------------------------------------------------------------
// Kernel A: per-chunk local end states (zero initial state)
// ---------------------------------------------------------------------------
__device__ __forceinline__ void stepA(u64* h, const u64* q, float xv) {
    u64 a = pack2(xv, xv);
#pragma unroll
    for (int j = 0; j < 8; j++) h[j] = fma2(q[j], h[j], a);
}

__global__ void __launch_bounds__(TD, 10) local_kernel(const float* __restrict__ x) {
    int d = blockIdx.x * TD + threadIdx.x;      // channel index
    int c = blockIdx.y, b = blockIdx.z;
    bool lane0 = (threadIdx.x & 31) == 0;
    u64 q[8], h[8];
#pragma unroll
    for (int j = 0; j < 8; j++) {
        float2 v = *(const float2*)(g_q + d * cN + 2 * j);
        q[j] = pack2(v.x, v.y);
        h[j] = 0ULL;
    }
    const float* xp = x + ((size_t)b * cL + (size_t)c * cS) * cD + d;
    float x0 = xp[0], x1 = xp[cD], x2 = xp[2 * cD], x3 = xp[3 * cD];
#pragma unroll 1
    for (int t = 0; t < cS; t += 4) {
        if (lane0 && t + 8 < cS) {              // L2 prefetch 2 iters ahead
            pf_l2(xp + 8 * cD);  pf_l2(xp + 9 * cD);
            pf_l2(xp + 10 * cD); pf_l2(xp + 11 * cD);
        }
        float y0, y1, y2, y3;
        if (t + 4 < cS) {
            y0 = xp[4 * cD]; y1 = xp[5 * cD]; y2 = xp[6 * cD]; y3 = xp[7 * cD];
        }
        stepA(h, q, x0); stepA(h, q, x1); stepA(h, q, x2); stepA(h, q, x3);
        xp += 4 * cD;
        x0 = y0; x1 = y1; x2 = y2; x3 = y3;
    }
    size_t pb = ((size_t)(b * cC + c) * cD + d) * cN;
#pragma unroll
    for (int j = 0; j < 8; j++)
        *(float2*)(g_Le + pb + 2 * j) = unpack2(h[j]);
}

// ---------------------------------------------------------------------------
// Kernel B: scan across chunks: P[c] = E[c-1], E[c] = q^S * E[c-1] + Le[c]
// ---------------------------------------------------------------------------
__global__ void scan_kernel() {
    int i = blockIdx.x * blockDim.x + threadIdx.x;
    if (i >= cB * cD * cN) return;
    int dn = i % (cD * cN);
    int b  = i / (cD * cN);
    float qS = g_qS[dn];
    size_t base = (size_t)b * cC * cD * cN + dn;
    float h = 0.f;
#pragma unroll
    for (int c = 0; c < cC; c++) {
        g_P[base + (size_t)c * cD * cN] = h;
        h = fmaf(qS, h, g_Le[base + (size_t)c * cD * cN]);
    }
}

// ---------------------------------------------------------------------------
// Kernel C: full recurrence per chunk with correct initial state + residual
// ---------------------------------------------------------------------------
__device__ __forceinline__ float stepC(u64* h, const u64* q, const u64* cc,
                                       float xv, float w) {
    u64 a = pack2(xv, xv);
#pragma unroll
    for (int j = 0; j < 8; j++) h[j] = fma2(q[j], h[j], a);
    u64 s0 = mul2(cc[0], h[0]);
    u64 s1 = mul2(cc[1], h[1]);
    s0 = fma2(cc[2], h[2], s0);  s1 = fma2(cc[3], h[3], s1);
    s0 = fma2(cc[4], h[4], s0);  s1 = fma2(cc[5], h[5], s1);
    s0 = fma2(cc[6], h[6], s0);  s1 = fma2(cc[7], h[7], s1);
    float2 f = unpack2(add2(s0, s1));
    return fmaf(xv, w, f.x + f.y);
}

__global__ void __launch_bounds__(TD, 7) main_kernel(const float* __restrict__ x,
                                                     const float* __restrict__ omega,
                                                     float* __restrict__ out) {
    int d = blockIdx.x * TD + threadIdx.x;      // channel index
    int c = blockIdx.y, b = blockIdx.z;
    bool lane0 = (threadIdx.x & 31) == 0;
    u64 q[8], cc[8], h[8];
    size_t pb = ((size_t)(b * cC + c) * cD + d) * cN;
#pragma unroll
    for (int j = 0; j < 8; j++) {
        float2 v  = *(const float2*)(g_q  + d * cN + 2 * j);
        float2 cv = *(const float2*)(g_cc + d * cN + 2 * j);
        float2 hv = *(const float2*)(g_P  + pb + 2 * j);
        q[j]  = pack2(v.x, v.y);
        cc[j] = pack2(cv.x, cv.y);
        h[j]  = pack2(hv.x, hv.y);
    }
    float w = omega[d];
    size_t off = ((size_t)b * cL + (size_t)c * cS) * cD + d;
    const float* xp = x + off;
    float* op = out + off;
    float x0 = xp[0], x1 = xp[cD], x2 = xp[2 * cD], x3 = xp[3 * cD];
#pragma unroll 1
    for (int t = 0; t < cS; t += 4) {
        if (lane0 && t + 8 < cS) {              // L2 prefetch 2 iters ahead
            pf_l2(xp + 8 * cD);  pf_l2(xp + 9 * cD);
            pf_l2(xp + 10 * cD); pf_l2(xp + 11 * cD);
        }
        float y0, y1, y2, y3;
        if (t + 4 < cS) {
            y0 = xp[4 * cD]; y1 = xp[5 * cD]; y2 = xp[6 * cD]; y3 = xp[7 * cD];
        }
        op[0]      = stepC(h, q, cc, x0, w);
        op[cD]     = stepC(h, q, cc, x1, w);
        op[2 * cD] = stepC(h, q, cc, x2, w);
        op[3 * cD] = stepC(h, q, cc, x3, w);
        xp += 4 * cD;
        op += 4 * cD;
        x0 = y0; x1 = y1; x2 = y2; x3 = y3;
    }
}

// ---------------------------------------------------------------------------
extern "C" void kernel_launch(void* const* d_in, const int* in_sizes, int n_in,
                              void* d_out, int out_size) {
    const float* x     = (const float*)d_in[0];
    const float* delta = (const float*)d_in[1];
    const float* alpha = (const float*)d_in[2];
    const float* beta  = (const float*)d_in[3];
    const float* gamma = (const float*)d_in[4];
    const float* omega = (const float*)d_in[5];
    float* out = (float*)d_out;

    coeff_kernel<<<(cD * cN + 255) / 256, 256>>>(delta, alpha, beta, gamma);
    dim3 grid(cD / TD, cC, cB);                 // (8, 32, 8) = 2048 CTAs
    local_kernel<<<grid, TD>>>(x);
    scan_kernel<<<(cB * cD * cN + 255) / 256, 256>>>();
    main_kernel<<<grid, TD>>>(x, omega, out);
}

// round 8
// speedup vs baseline: 1.2979x; 1.2979x over previous
#include <cuda_runtime.h>
#include <cstdint>

// MultiHeadEMA as a chunked diagonal linear recurrence (no FFT).
// out[b,t,d] = sum_n c[d,n] * h[d,n,t] + omega[d]*x[b,t,d]
// h[t] = q*h[t-1] + x[t],  q = 1 - sigmoid(delta)*sigmoid(alpha),
// c = sigmoid(delta)*beta*gamma*sqrt(1/N)
//
// R6 (= R5 + compile fix): cp.async 3-stage smem pipeline for x (decouple
// DRAM latency from the h-recurrence), C=16 so grid(1024) = one wave at
// 7 CTAs/SM.

#define cB 8
#define cL 4096
#define cD 1024
#define cN 16
#define cC 16            // chunks
#define cS (cL / cC)     // 256 steps per chunk
#define TD 128           // threads per block (1 channel per thread)
#define ST 16            // timesteps per smem stage
#define NSTG 3           // pipeline stages
#define NSTAGE_ITERS (cS / ST)   // 16

typedef unsigned long long u64;
typedef unsigned int u32;

// scratch (static __device__ arrays: no allocations allowed)
__device__ float g_q[cD * cN];
__device__ float g_cc[cD * cN];
__device__ float g_qS[cD * cN];
__device__ float g_Le[(size_t)cB * cC * cD * cN];  // local chunk end states
__device__ float g_P[(size_t)cB * cC * cD * cN];   // prefix (init) states per chunk

__device__ __forceinline__ u64 pack2(float lo, float hi) {
    u64 r; asm("mov.b64 %0,{%1,%2};" : "=l"(r) : "f"(lo), "f"(hi)); return r;
}
__device__ __forceinline__ float2 unpack2(u64 v) {
    float2 f; asm("mov.b64 {%0,%1},%2;" : "=f"(f.x), "=f"(f.y) : "l"(v)); return f;
}
__device__ __forceinline__ u64 fma2(u64 a, u64 b, u64 c) {
    u64 d; asm("fma.rn.f32x2 %0,%1,%2,%3;" : "=l"(d) : "l"(a), "l"(b), "l"(c)); return d;
}
__device__ __forceinline__ u64 mul2(u64 a, u64 b) {
    u64 d; asm("mul.rn.f32x2 %0,%1,%2;" : "=l"(d) : "l"(a), "l"(b)); return d;
}
__device__ __forceinline__ u64 add2(u64 a, u64 b) {
    u64 d; asm("add.rn.f32x2 %0,%1,%2;" : "=l"(d) : "l"(a), "l"(b)); return d;
}
__device__ __forceinline__ void cp16(u32 saddr, const float* g) {
    asm volatile("cp.async.ca.shared.global [%0], [%1], 16;" :: "r"(saddr), "l"(g));
}
__device__ __forceinline__ void cp_commit() {
    asm volatile("cp.async.commit_group;");
}
__device__ __forceinline__ void cp_wait1() {
    asm volatile("cp.async.wait_group 1;");
}

// Issue one stage's tile (ST x TD floats) via cp.async. gbase = x-block base
// (already offset by b, chunk, d-block). Each thread copies 4x 16B.
__device__ __forceinline__ void issue_stage(const float* gbase, int st,
                                            float* sbuf /* stage buffer base */) {
    const float* g0 = gbase + (size_t)(st * ST) * cD;
    int col4 = (threadIdx.x & 31) * 4;
    int r0 = threadIdx.x >> 5;
#pragma unroll
    for (int k = 0; k < 4; k++) {
        int row = r0 + 4 * k;
        u32 s = (u32)__cvta_generic_to_shared(sbuf + row * TD + col4);
        cp16(s, g0 + (size_t)row * cD + col4);
    }
}

// ---------------------------------------------------------------------------
// Kernel 0: per-(d,n) coefficients
// ---------------------------------------------------------------------------
__global__ void coeff_kernel(const float* __restrict__ delta,
                             const float* __restrict__ alpha,
                             const float* __restrict__ beta,
                             const float* __restrict__ gamma) {
    int i = blockIdx.x * blockDim.x + threadIdx.x;
    if (i >= cD * cN) return;
    float p  = 1.f / (1.f + expf(-delta[i]));
    float a  = 1.f / (1.f + expf(-alpha[i]));
    float pa = p * a;
    g_q[i]  = 1.f - pa;
    g_cc[i] = p * beta[i] * gamma[i] * 0.25f;               // scale = sqrt(1/16)
    g_qS[i] = expf((float)cS * log1pf(-pa));                // q^S, accurate near q~1
}

// ---------------------------------------------------------------------------
// Kernel A: per-chunk local end states (zero initial state)
// ---------------------------------------------------------------------------
__global__ void __launch_bounds__(TD, 7) local_kernel(const float* __restrict__ x) {
    __shared__ float sx[NSTG][ST][TD];          // 24 KB
    int d = blockIdx.x * TD + threadIdx.x;
    int c = blockIdx.y, b = blockIdx.z;
    u64 q[8], h[8];
#pragma unroll
    for (int j = 0; j < 8; j++) {
        float2 v = *(const float2*)(g_q + d * cN + 2 * j);
        q[j] = pack2(v.x, v.y);
        h[j] = 0ULL;
    }
    const float* gbase = x + ((size_t)b * cL + (size_t)c * cS) * cD
                           + (size_t)blockIdx.x * TD;
    issue_stage(gbase, 0, &sx[0][0][0]); cp_commit();
    issue_stage(gbase, 1, &sx[1][0][0]); cp_commit();

#pragma unroll 1
    for (int s = 0; s < NSTAGE_ITERS; s++) {
        cp_wait1();
        __syncthreads();
        if (s + 2 < NSTAGE_ITERS)
            issue_stage(gbase, s + 2, &sx[(s + 2) % NSTG][0][0]);
        cp_commit();                            // uniform group count
        const float* sp = &sx[s % NSTG][0][0] + threadIdx.x;
#pragma unroll
        for (int tt = 0; tt < ST; tt++) {
            float xv = sp[tt * TD];
            u64 a = pack2(xv, xv);
#pragma unroll
            for (int j = 0; j < 8; j++) h[j] = fma2(q[j], h[j], a);
        }
    }
    size_t pb = ((size_t)(b * cC + c) * cD + d) * cN;
#pragma unroll
    for (int j = 0; j < 8; j++)
        *(float2*)(g_Le + pb + 2 * j) = unpack2(h[j]);
}

// ---------------------------------------------------------------------------
// Kernel B: scan across chunks: P[c] = E[c-1], E[c] = q^S * E[c-1] + Le[c]
// ---------------------------------------------------------------------------
__global__ void scan_kernel() {
    int i = blockIdx.x * blockDim.x + threadIdx.x;
    if (i >= cB * cD * cN) return;
    int dn = i % (cD * cN);
    int b  = i / (cD * cN);
    float qS = g_qS[dn];
    size_t base = (size_t)b * cC * cD * cN + dn;
    float h = 0.f;
#pragma unroll
    for (int c = 0; c < cC; c++) {
        g_P[base + (size_t)c * cD * cN] = h;
        h = fmaf(qS, h, g_Le[base + (size_t)c * cD * cN]);
    }
}

// ---------------------------------------------------------------------------
// Kernel C: full recurrence per chunk with correct initial state + residual
// ---------------------------------------------------------------------------
__device__ __forceinline__ float stepC(u64* h, const u64* q, const u64* cc,
                                       float xv, float w) {
    u64 a = pack2(xv, xv);
#pragma unroll
    for (int j = 0; j < 8; j++) h[j] = fma2(q[j], h[j], a);
    u64 s0 = mul2(cc[0], h[0]);
    u64 s1 = mul2(cc[1], h[1]);
    s0 = fma2(cc[2], h[2], s0);  s1 = fma2(cc[3], h[3], s1);
    s0 = fma2(cc[4], h[4], s0);  s1 = fma2(cc[5], h[5], s1);
    s0 = fma2(cc[6], h[6], s0);  s1 = fma2(cc[7], h[7], s1);
    float2 f = unpack2(add2(s0, s1));
    return fmaf(xv, w, f.x + f.y);
}

__global__ void __launch_bounds__(TD, 7) main_kernel(const float* __restrict__ x,
                                                     const float* __restrict__ omega,
                                                     float* __restrict__ out) {
    __shared__ float sx[NSTG][ST][TD];          // 24 KB
    int d = blockIdx.x * TD + threadIdx.x;
    int c = blockIdx.y, b = blockIdx.z;
    u64 q[8], cc[8], h[8];
    size_t pb = ((size_t)(b * cC + c) * cD + d) * cN;
#pragma unroll
    for (int j = 0; j < 8; j++) {
        float2 v  = *(const float2*)(g_q  + d * cN + 2 * j);
        float2 cv = *(const float2*)(g_cc + d * cN + 2 * j);
        float2 hv = *(const float2*)(g_P  + pb + 2 * j);
        q[j]  = pack2(v.x, v.y);
        cc[j] = pack2(cv.x, cv.y);
        h[j]  = pack2(hv.x, hv.y);
    }
    float w = omega[d];
    const float* gbase = x + ((size_t)b * cL + (size_t)c * cS) * cD
                           + (size_t)blockIdx.x * TD;
    float* op = out + ((size_t)b * cL + (size_t)c * cS) * cD + d;

    issue_stage(gbase, 0, &sx[0][0][0]); cp_commit();
    issue_stage(gbase, 1, &sx[1][0][0]); cp_commit();

#pragma unroll 1
    for (int s = 0; s < NSTAGE_ITERS; s++) {
        cp_wait1();
        __syncthreads();
        if (s + 2 < NSTAGE_ITERS)
            issue_stage(gbase, s + 2, &sx[(s + 2) % NSTG][0][0]);
        cp_commit();                            // uniform group count
        const float* sp = &sx[s % NSTG][0][0] + threadIdx.x;
#pragma unroll
        for (int tt = 0; tt < ST; tt++) {
            float xv = sp[tt * TD];
            op[(size_t)tt * cD] = stepC(h, q, cc, xv, w);
        }
        op += (size_t)ST * cD;
    }
}

// ---------------------------------------------------------------------------
extern "C" void kernel_launch(void* const* d_in, const int* in_sizes, int n_in,
                              void* d_out, int out_size) {
    const float* x     = (const float*)d_in[0];
    const float* delta = (const float*)d_in[1];
    const float* alpha = (const float*)d_in[2];
    const float* beta  = (const float*)d_in[3];
    const float* gamma = (const float*)d_in[4];
    const float* omega = (const float*)d_in[5];
    float* out = (float*)d_out;

    coeff_kernel<<<(cD * cN + 255) / 256, 256>>>(delta, alpha, beta, gamma);
    dim3 grid(cD / TD, cC, cB);                 // (8, 16, 8) = 1024 CTAs
    local_kernel<<<grid, TD>>>(x);
    scan_kernel<<<(cB * cD * cN + 255) / 256, 256>>>();
    main_kernel<<<grid, TD>>>(x, omega, out);
}